// round 3
// baseline (speedup 1.0000x reference)
#include <cuda_runtime.h>
#include <math.h>
#include <stdint.h>

// Problem constants
#define TT 8192      // tokens = B*S
#define HD 1024      // hidden
#define FD 4096      // ffn
#define NE 8         // experts
#define NSLOT (TT*2) // token-expert pairs (top-2)

// Scratch (device globals — no allocations allowed)
__device__ int   g_cnt[NE];
__device__ int   g_off[NE];
__device__ int   g_cur[NE];
__device__ int   g_topi[TT*2];
__device__ float g_topw[TT*2];
__device__ int   g_perm[NSLOT];
__device__ float g_gw[NSLOT];
__device__ float g_h1[(size_t)NSLOT * FD];   // 256 MB intermediate activations

// ---------------------------------------------------------------------------
// Zero output + expert counters
// ---------------------------------------------------------------------------
__global__ void zero_kernel(float4* __restrict__ out4) {
    unsigned i = blockIdx.x * blockDim.x + threadIdx.x;   // 4096*256 = 1,048,576 threads
    const float4 z = make_float4(0.f, 0.f, 0.f, 0.f);
    out4[i] = z;                       // first half of 2,097,152 float4
    out4[i + (TT * HD / 8)] = z;       // second half
    if (i < NE) g_cnt[i] = 0;
}

// ---------------------------------------------------------------------------
// Router: one warp per token. logits = x @ router_w + b; top-2; renormalize.
// softmax+topk+renorm == 2-way softmax over the top-2 logits.
// ---------------------------------------------------------------------------
__global__ void router_kernel(const float* __restrict__ x,
                              const float* __restrict__ rw,
                              const float* __restrict__ rb) {
    int t    = (blockIdx.x * blockDim.x + threadIdx.x) >> 5;
    int lane = threadIdx.x & 31;
    if (t >= TT) return;

    const float* xp = x + (size_t)t * HD;
    float acc[NE];
#pragma unroll
    for (int e = 0; e < NE; e++) acc[e] = 0.f;

    for (int h = lane; h < HD; h += 32) {
        float xv = xp[h];
        const float4* r = (const float4*)(rw + (size_t)h * NE);
        float4 a = r[0], b = r[1];
        acc[0] += xv * a.x; acc[1] += xv * a.y; acc[2] += xv * a.z; acc[3] += xv * a.w;
        acc[4] += xv * b.x; acc[5] += xv * b.y; acc[6] += xv * b.z; acc[7] += xv * b.w;
    }
#pragma unroll
    for (int e = 0; e < NE; e++)
#pragma unroll
        for (int o = 16; o > 0; o >>= 1)
            acc[e] += __shfl_xor_sync(0xffffffffu, acc[e], o);

    if (lane == 0) {
        float l[NE];
#pragma unroll
        for (int e = 0; e < NE; e++) l[e] = acc[e] + rb[e];
        // top-1 (lowest index wins ties, matching jax.lax.top_k)
        int i1 = 0;
#pragma unroll
        for (int e = 1; e < NE; e++) if (l[e] > l[i1]) i1 = e;
        // top-2
        int i2 = (i1 == 0) ? 1 : 0;
#pragma unroll
        for (int e = 0; e < NE; e++) if (e != i1 && l[e] > l[i2]) i2 = e;

        float d  = expf(l[i2] - l[i1]);     // <= 1
        float w1 = 1.f / (1.f + d);
        float w2 = d * w1;
        g_topi[2 * t + 0] = i1; g_topw[2 * t + 0] = w1;
        g_topi[2 * t + 1] = i2; g_topw[2 * t + 1] = w2;
        atomicAdd(&g_cnt[i1], 1);
        atomicAdd(&g_cnt[i2], 1);
    }
}

// ---------------------------------------------------------------------------
// Exclusive prefix over 8 counts (trivial)
// ---------------------------------------------------------------------------
__global__ void prefix_kernel() {
    if (threadIdx.x == 0) {
        int s = 0;
        for (int e = 0; e < NE; e++) { g_off[e] = s; g_cur[e] = s; s += g_cnt[e]; }
    }
}

// ---------------------------------------------------------------------------
// Scatter tokens into per-expert segments
// ---------------------------------------------------------------------------
__global__ void scatter_kernel() {
    int t = blockIdx.x * blockDim.x + threadIdx.x;
    if (t >= TT) return;
#pragma unroll
    for (int k = 0; k < 2; k++) {
        int e = g_topi[2 * t + k];
        int p = atomicAdd(&g_cur[e], 1);
        g_perm[p] = t;
        g_gw[p]   = g_topw[2 * t + k];
    }
}

// ---------------------------------------------------------------------------
// Grouped GEMM, 128x128 tile, BK=8, 256 threads, 8x8 register micro-tile.
// MODE 0: h1[slot] = gelu_tanh(gather(x) @ w1[e] + b1[e])     (K=HD, N=FD)
// MODE 1: out[tok] += gw * (h1[slot] @ w2[e] + b2[e])          (K=FD, N=HD)
// ---------------------------------------------------------------------------
template <int MODE>
__global__ void __launch_bounds__(256, 2) moe_gemm_kernel(
    const float* __restrict__ x_base,
    const float* __restrict__ B_base,
    const float* __restrict__ bias,
    float* __restrict__ out)
{
    constexpr int KD = (MODE == 0) ? HD : FD;
    constexpr int ND = (MODE == 0) ? FD : HD;

    const int e       = blockIdx.z;
    const int seg_len = g_cnt[e];
    const int m0      = blockIdx.x * 128;
    if (m0 >= seg_len) return;
    const int seg_off = g_off[e];
    const int n0      = blockIdx.y * 128;

    __shared__ __align__(16) float As[2][8][128];
    __shared__ __align__(16) float Bs[2][8][128];
    __shared__ const float* Arow[128];

    const int tid  = threadIdx.x;
    const int aRow = tid >> 1;          // 0..127
    const int aK   = (tid & 1) << 2;    // 0 or 4
    const int bRow = tid >> 5;          // 0..7
    const int bCol = (tid & 31) << 2;   // 0..124

    if (tid < 128) {
        int gr = m0 + tid;
        const float* p = nullptr;
        if (gr < seg_len) {
            if (MODE == 0) p = x_base + (size_t)g_perm[seg_off + gr] * (size_t)KD;
            else           p = g_h1   + (size_t)(seg_off + gr) * (size_t)KD;
        }
        Arow[tid] = p;
    }
    __syncthreads();

    const float* aP = Arow[aRow];
    const float* Bp = B_base + (size_t)e * KD * ND + n0;

    float acc[8][8];
#pragma unroll
    for (int i = 0; i < 8; i++)
#pragma unroll
        for (int j = 0; j < 8; j++) acc[i][j] = 0.f;

    auto load_tiles = [&](int buf, int kt) {
        float4 av = make_float4(0.f, 0.f, 0.f, 0.f);
        if (aP) av = *(const float4*)(aP + kt + aK);
        As[buf][aK + 0][aRow] = av.x;
        As[buf][aK + 1][aRow] = av.y;
        As[buf][aK + 2][aRow] = av.z;
        As[buf][aK + 3][aRow] = av.w;
        float4 bv = *(const float4*)(Bp + (size_t)(kt + bRow) * ND + bCol);
        *(float4*)&Bs[buf][bRow][bCol] = bv;
    };

    load_tiles(0, 0);
    __syncthreads();

    const int cr = (tid >> 4) << 3;   // 0..120
    const int cc = (tid & 15) << 3;   // 0..120

    int buf = 0;
    for (int kt = 0; kt < KD; kt += 8) {
        if (kt + 8 < KD) load_tiles(buf ^ 1, kt + 8);
#pragma unroll
        for (int k = 0; k < 8; k++) {
            float4 a0 = *(const float4*)&As[buf][k][cr];
            float4 a1 = *(const float4*)&As[buf][k][cr + 4];
            float4 b0 = *(const float4*)&Bs[buf][k][cc];
            float4 b1 = *(const float4*)&Bs[buf][k][cc + 4];
            float a[8] = {a0.x, a0.y, a0.z, a0.w, a1.x, a1.y, a1.z, a1.w};
            float b[8] = {b0.x, b0.y, b0.z, b0.w, b1.x, b1.y, b1.z, b1.w};
#pragma unroll
            for (int i = 0; i < 8; i++)
#pragma unroll
                for (int j = 0; j < 8; j++)
                    acc[i][j] += a[i] * b[j];
        }
        __syncthreads();
        buf ^= 1;
    }

    if (MODE == 0) {
#pragma unroll
        for (int i = 0; i < 8; i++) {
            int gr = m0 + cr + i;
            if (gr < seg_len) {
                size_t slot = (size_t)(seg_off + gr);
                float*       op = g_h1 + slot * FD + n0 + cc;
                const float* bp = bias + (size_t)e * ND + n0 + cc;
#pragma unroll
                for (int j = 0; j < 8; j++) {
                    float v = acc[i][j] + bp[j];
                    float c = v + 0.044715f * v * v * v;
                    float t = tanhf(0.7978845608028654f * c);
                    op[j] = 0.5f * v * (1.f + t);
                }
            }
        }
    } else {
#pragma unroll
        for (int i = 0; i < 8; i++) {
            int gr = m0 + cr + i;
            if (gr < seg_len) {
                int   slot = seg_off + gr;
                int   tok  = g_perm[slot];
                float w    = g_gw[slot];
                float*       op = out  + (size_t)tok * HD + n0 + cc;
                const float* bp = bias + (size_t)e * ND + n0 + cc;
#pragma unroll
                for (int j = 0; j < 8; j++)
                    atomicAdd(&op[j], w * (acc[i][j] + bp[j]));
            }
        }
    }
}

// ---------------------------------------------------------------------------
// Launch
// ---------------------------------------------------------------------------
extern "C" void kernel_launch(void* const* d_in, const int* in_sizes, int n_in,
                              void* d_out, int out_size) {
    const float* x  = (const float*)d_in[0];   // [B,S,H]
    const float* w1 = (const float*)d_in[1];   // [E,H,F]
    const float* b1 = (const float*)d_in[2];   // [E,F]
    const float* w2 = (const float*)d_in[3];   // [E,F,H]
    const float* b2 = (const float*)d_in[4];   // [E,H]
    const float* rw = (const float*)d_in[5];   // [H,E]
    const float* rb = (const float*)d_in[6];   // [E]
    float* out = (float*)d_out;

    zero_kernel<<<4096, 256>>>((float4*)out);
    router_kernel<<<TT / 8, 256>>>(x, rw, rb);
    prefix_kernel<<<1, 32>>>();
    scatter_kernel<<<TT / 256, 256>>>();

    // GEMM1: gather(x) @ w1 + b1 -> gelu -> h1   (grid covers worst-case seg len)
    moe_gemm_kernel<0><<<dim3(64, FD / 128, NE), 256>>>(x, w1, b1, nullptr);
    // GEMM2: h1 @ w2 + b2, weighted scatter-add into out
    moe_gemm_kernel<1><<<dim3(64, HD / 128, NE), 256>>>(x, w2, b2, out);
}

// round 5
// speedup vs baseline: 1.7701x; 1.7701x over previous
#include <cuda_runtime.h>
#include <math.h>
#include <stdint.h>

// Problem constants
#define TT 8192      // tokens = B*S
#define HD 1024      // hidden
#define FD 4096      // ffn
#define NE 8         // experts
#define NSLOT (TT*2) // token-expert pairs (top-2)

typedef unsigned long long ull;

// Scratch (device globals — no allocations allowed)
__device__ int   g_cnt[NE];
__device__ int   g_off[NE];
__device__ int   g_cur[NE];
__device__ int   g_topi[TT*2];
__device__ float g_topw[TT*2];
__device__ int   g_perm[NSLOT];
__device__ float g_gw[NSLOT];
__device__ float g_h1[(size_t)NSLOT * FD];   // 256 MB intermediate activations

// ---- packed fp32x2 helpers (FFMA2 — ptxas never emits this from C++) ----
__device__ __forceinline__ ull pack2(float lo, float hi) {
    ull r; asm("mov.b64 %0, {%1, %2};" : "=l"(r) : "f"(lo), "f"(hi)); return r;
}
__device__ __forceinline__ void unpack2(ull v, float& lo, float& hi) {
    asm("mov.b64 {%0, %1}, %2;" : "=f"(lo), "=f"(hi) : "l"(v));
}
__device__ __forceinline__ ull fma2(ull a, ull b, ull c) {
    ull d; asm("fma.rn.f32x2 %0, %1, %2, %3;" : "=l"(d) : "l"(a), "l"(b), "l"(c)); return d;
}

// ---------------------------------------------------------------------------
// Zero output + expert counters
// ---------------------------------------------------------------------------
__global__ void zero_kernel(float4* __restrict__ out4) {
    unsigned i = blockIdx.x * blockDim.x + threadIdx.x;
    const float4 z = make_float4(0.f, 0.f, 0.f, 0.f);
    out4[i] = z;
    out4[i + (TT * HD / 8)] = z;
    if (i < NE) g_cnt[i] = 0;
}

// ---------------------------------------------------------------------------
// Router: one warp per token. logits = x @ router_w + b; top-2; renormalize.
// ---------------------------------------------------------------------------
__global__ void router_kernel(const float* __restrict__ x,
                              const float* __restrict__ rw,
                              const float* __restrict__ rb) {
    int t    = (blockIdx.x * blockDim.x + threadIdx.x) >> 5;
    int lane = threadIdx.x & 31;
    if (t >= TT) return;

    const float* xp = x + (size_t)t * HD;
    float acc[NE];
#pragma unroll
    for (int e = 0; e < NE; e++) acc[e] = 0.f;

    for (int h = lane; h < HD; h += 32) {
        float xv = xp[h];
        const float4* r = (const float4*)(rw + (size_t)h * NE);
        float4 a = r[0], b = r[1];
        acc[0] += xv * a.x; acc[1] += xv * a.y; acc[2] += xv * a.z; acc[3] += xv * a.w;
        acc[4] += xv * b.x; acc[5] += xv * b.y; acc[6] += xv * b.z; acc[7] += xv * b.w;
    }
#pragma unroll
    for (int e = 0; e < NE; e++)
#pragma unroll
        for (int o = 16; o > 0; o >>= 1)
            acc[e] += __shfl_xor_sync(0xffffffffu, acc[e], o);

    if (lane == 0) {
        float l[NE];
#pragma unroll
        for (int e = 0; e < NE; e++) l[e] = acc[e] + rb[e];
        int i1 = 0;
#pragma unroll
        for (int e = 1; e < NE; e++) if (l[e] > l[i1]) i1 = e;
        int i2 = (i1 == 0) ? 1 : 0;
#pragma unroll
        for (int e = 0; e < NE; e++) if (e != i1 && l[e] > l[i2]) i2 = e;

        float d  = expf(l[i2] - l[i1]);
        float w1 = 1.f / (1.f + d);
        float w2 = d * w1;
        g_topi[2 * t + 0] = i1; g_topw[2 * t + 0] = w1;
        g_topi[2 * t + 1] = i2; g_topw[2 * t + 1] = w2;
        atomicAdd(&g_cnt[i1], 1);
        atomicAdd(&g_cnt[i2], 1);
    }
}

__global__ void prefix_kernel() {
    if (threadIdx.x == 0) {
        int s = 0;
        for (int e = 0; e < NE; e++) { g_off[e] = s; g_cur[e] = s; s += g_cnt[e]; }
    }
}

__global__ void scatter_kernel() {
    int t = blockIdx.x * blockDim.x + threadIdx.x;
    if (t >= TT) return;
#pragma unroll
    for (int k = 0; k < 2; k++) {
        int e = g_topi[2 * t + k];
        int p = atomicAdd(&g_cur[e], 1);
        g_perm[p] = t;
        g_gw[p]   = g_topw[2 * t + k];
    }
}

// ---------------------------------------------------------------------------
// Grouped GEMM, 128x128 tile, BK=8, 256 threads, 8x8 micro-tile, packed f32x2.
// MODE 0: h1[slot] = gelu_tanh(gather(x) @ w1[e] + b1[e])     (K=HD, N=FD)
// MODE 1: out[tok] += gw * (h1[slot] @ w2[e] + b2[e])          (K=FD, N=HD)
// ---------------------------------------------------------------------------
template <int MODE>
__global__ void __launch_bounds__(256, 2) moe_gemm_kernel(
    const float* __restrict__ x_base,
    const float* __restrict__ B_base,
    const float* __restrict__ bias,
    float* __restrict__ out)
{
    constexpr int KD = (MODE == 0) ? HD : FD;
    constexpr int ND = (MODE == 0) ? FD : HD;

    const int e       = blockIdx.z;
    const int seg_len = g_cnt[e];
    const int m0      = blockIdx.x * 128;
    if (m0 >= seg_len) return;
    const int seg_off = g_off[e];
    const int n0      = blockIdx.y * 128;

    __shared__ __align__(16) float As[2][8][128];
    __shared__ __align__(16) float Bs[2][8][128];
    __shared__ const float* Arow[128];

    const int tid  = threadIdx.x;
    const int aRow = tid >> 1;
    const int aK   = (tid & 1) << 2;
    const int bRow = tid >> 5;
    const int bCol = (tid & 31) << 2;

    if (tid < 128) {
        int gr = m0 + tid;
        const float* p = nullptr;
        if (gr < seg_len) {
            if (MODE == 0) p = x_base + (size_t)g_perm[seg_off + gr] * (size_t)KD;
            else           p = g_h1   + (size_t)(seg_off + gr) * (size_t)KD;
        }
        Arow[tid] = p;
    }
    __syncthreads();

    const float* aP = Arow[aRow];
    const float* Bp = B_base + (size_t)e * KD * ND + n0;

    ull acc2[8][4];
#pragma unroll
    for (int i = 0; i < 8; i++)
#pragma unroll
        for (int j = 0; j < 4; j++) acc2[i][j] = 0ULL;

    auto load_tiles = [&](int buf, int kt) {
        float4 av = make_float4(0.f, 0.f, 0.f, 0.f);
        if (aP) av = *(const float4*)(aP + kt + aK);
        As[buf][aK + 0][aRow] = av.x;
        As[buf][aK + 1][aRow] = av.y;
        As[buf][aK + 2][aRow] = av.z;
        As[buf][aK + 3][aRow] = av.w;
        float4 bv = *(const float4*)(Bp + (size_t)(kt + bRow) * ND + bCol);
        *(float4*)&Bs[buf][bRow][bCol] = bv;
    };

    load_tiles(0, 0);
    __syncthreads();

    const int cr = (tid >> 4) << 3;   // 0..120
    const int cc = (tid & 15) << 3;   // 0..120

    int buf = 0;
    for (int kt = 0; kt < KD; kt += 8) {
        if (kt + 8 < KD) load_tiles(buf ^ 1, kt + 8);
#pragma unroll
        for (int k = 0; k < 8; k++) {
            float4 a0 = *(const float4*)&As[buf][k][cr];
            float4 a1 = *(const float4*)&As[buf][k][cr + 4];
            float4 b0 = *(const float4*)&Bs[buf][k][cc];
            float4 b1 = *(const float4*)&Bs[buf][k][cc + 4];
            ull bp2[4];
            bp2[0] = pack2(b0.x, b0.y);
            bp2[1] = pack2(b0.z, b0.w);
            bp2[2] = pack2(b1.x, b1.y);
            bp2[3] = pack2(b1.z, b1.w);
            float a[8] = {a0.x, a0.y, a0.z, a0.w, a1.x, a1.y, a1.z, a1.w};
#pragma unroll
            for (int i = 0; i < 8; i++) {
                ull ai = pack2(a[i], a[i]);
#pragma unroll
                for (int j = 0; j < 4; j++)
                    acc2[i][j] = fma2(ai, bp2[j], acc2[i][j]);
            }
        }
        __syncthreads();
        buf ^= 1;
    }

    if (MODE == 0) {
#pragma unroll
        for (int i = 0; i < 8; i++) {
            int gr = m0 + cr + i;
            if (gr < seg_len) {
                size_t slot = (size_t)(seg_off + gr);
                float*       op = g_h1 + slot * FD + n0 + cc;
                const float* bp = bias + (size_t)e * ND + n0 + cc;
                float av[8];
#pragma unroll
                for (int j = 0; j < 4; j++) unpack2(acc2[i][j], av[2*j], av[2*j+1]);
#pragma unroll
                for (int j = 0; j < 8; j++) {
                    float v = av[j] + bp[j];
                    float c = v + 0.044715f * v * v * v;
                    float t = tanhf(0.7978845608028654f * c);
                    op[j] = 0.5f * v * (1.f + t);
                }
            }
        }
    } else {
#pragma unroll
        for (int i = 0; i < 8; i++) {
            int gr = m0 + cr + i;
            if (gr < seg_len) {
                int   slot = seg_off + gr;
                int   tok  = g_perm[slot];
                float w    = g_gw[slot];
                float*       op = out  + (size_t)tok * HD + n0 + cc;
                const float* bp = bias + (size_t)e * ND + n0 + cc;
                float av[8];
#pragma unroll
                for (int j = 0; j < 4; j++) unpack2(acc2[i][j], av[2*j], av[2*j+1]);
#pragma unroll
                for (int j = 0; j < 8; j++)
                    atomicAdd(&op[j], w * (av[j] + bp[j]));
            }
        }
    }
}

// ---------------------------------------------------------------------------
// Launch
// ---------------------------------------------------------------------------
extern "C" void kernel_launch(void* const* d_in, const int* in_sizes, int n_in,
                              void* d_out, int out_size) {
    const float* x  = (const float*)d_in[0];   // [B,S,H]
    const float* w1 = (const float*)d_in[1];   // [E,H,F]
    const float* b1 = (const float*)d_in[2];   // [E,F]
    const float* w2 = (const float*)d_in[3];   // [E,F,H]
    const float* b2 = (const float*)d_in[4];   // [E,H]
    const float* rw = (const float*)d_in[5];   // [H,E]
    const float* rb = (const float*)d_in[6];   // [E]
    float* out = (float*)d_out;

    zero_kernel<<<4096, 256>>>((float4*)out);
    router_kernel<<<TT / 8, 256>>>(x, rw, rb);
    prefix_kernel<<<1, 32>>>();
    scatter_kernel<<<TT / 256, 256>>>();

    moe_gemm_kernel<0><<<dim3(64, FD / 128, NE), 256>>>(x, w1, b1, nullptr);
    moe_gemm_kernel<1><<<dim3(64, HD / 128, NE), 256>>>(x, w2, b2, out);
}

// round 10
// speedup vs baseline: 3.2571x; 1.8400x over previous
#include <cuda_runtime.h>
#include <cuda_bf16.h>
#include <math.h>
#include <stdint.h>

// Problem constants
#define TT 8192      // tokens = B*S
#define HD 1024      // hidden
#define FD 4096      // ffn
#define NE 8         // experts
#define NSLOT (TT*2) // token-expert pairs (top-2)

// GEMM tiling: block 128x128, BK=32, 256 threads (8 warps: 4M x 2N, warp 32x64)
#define BM 128
#define BN 128
#define BK 32
#define ROWA 144                  // A row: 64B hi | 64B lo | 16B pad
#define ROWBB 528                 // B row: 256B hi | 256B lo | 16B pad
#define ASMOFF 0
#define BSMOFF (128 * ROWA)       // 18432
#define SMEMB (128 * ROWA + 32 * ROWBB)   // 35328 B static

// -------------------- device global scratch (proven footprint) -------------
__device__ int   g_cnt[NE];
__device__ int   g_off[NE];
__device__ int   g_cur[NE];
__device__ int   g_topi[TT*2];
__device__ float g_topw[TT*2];
__device__ int   g_perm[NSLOT];
__device__ float g_gw[NSLOT];
__device__ float g_h1[(size_t)NSLOT * FD];   // 256 MB fp32 (same as R3 passing)

// -------------------- helpers ----------------------------------------------
__device__ __forceinline__ uint32_t smem_u32(const void* p) {
    uint32_t a;
    asm("{ .reg .u64 t; cvta.to.shared.u64 t, %1; cvt.u32.u64 %0, t; }"
        : "=r"(a) : "l"(p));
    return a;
}
__device__ __forceinline__ void ldsm4(uint32_t a, uint32_t r[4]) {
    asm volatile("ldmatrix.sync.aligned.m8n8.x4.shared.b16 {%0,%1,%2,%3}, [%4];"
                 : "=r"(r[0]), "=r"(r[1]), "=r"(r[2]), "=r"(r[3]) : "r"(a));
}
__device__ __forceinline__ void ldsm4t(uint32_t a, uint32_t r[4]) {
    asm volatile("ldmatrix.sync.aligned.m8n8.x4.trans.shared.b16 {%0,%1,%2,%3}, [%4];"
                 : "=r"(r[0]), "=r"(r[1]), "=r"(r[2]), "=r"(r[3]) : "r"(a));
}
__device__ __forceinline__ void mma16816(float d[4], const uint32_t a[4],
                                         uint32_t b0, uint32_t b1) {
    asm volatile(
        "mma.sync.aligned.m16n8k16.row.col.f32.bf16.bf16.f32 "
        "{%0,%1,%2,%3}, {%4,%5,%6,%7}, {%8,%9}, {%0,%1,%2,%3};"
        : "+f"(d[0]), "+f"(d[1]), "+f"(d[2]), "+f"(d[3])
        : "r"(a[0]), "r"(a[1]), "r"(a[2]), "r"(a[3]), "r"(b0), "r"(b1));
}
__device__ __forceinline__ uint32_t pack_bf2(__nv_bfloat16 a, __nv_bfloat16 b) {
    return (uint32_t)__bfloat16_as_ushort(a) | ((uint32_t)__bfloat16_as_ushort(b) << 16);
}
// split pair of floats -> packed bf16x2 hi and lo
__device__ __forceinline__ void split2(float v0, float v1, uint32_t& h, uint32_t& l) {
    __nv_bfloat16 h0 = __float2bfloat16(v0);
    __nv_bfloat16 h1 = __float2bfloat16(v1);
    __nv_bfloat16 l0 = __float2bfloat16(v0 - __bfloat162float(h0));
    __nv_bfloat16 l1 = __float2bfloat16(v1 - __bfloat162float(h1));
    h = pack_bf2(h0, h1);
    l = pack_bf2(l0, l1);
}

// ---------------------------------------------------------------------------
// Zero output + expert counters
// ---------------------------------------------------------------------------
__global__ void zero_kernel(float4* __restrict__ out4) {
    unsigned i = blockIdx.x * blockDim.x + threadIdx.x;
    const float4 z = make_float4(0.f, 0.f, 0.f, 0.f);
    out4[i] = z;
    out4[i + (TT * HD / 8)] = z;
    if (i < NE) g_cnt[i] = 0;
}

// ---------------------------------------------------------------------------
// Router: one warp per token (proven)
// ---------------------------------------------------------------------------
__global__ void router_kernel(const float* __restrict__ x,
                              const float* __restrict__ rw,
                              const float* __restrict__ rb) {
    int t    = (blockIdx.x * blockDim.x + threadIdx.x) >> 5;
    int lane = threadIdx.x & 31;
    if (t >= TT) return;

    const float* xp = x + (size_t)t * HD;
    float acc[NE];
#pragma unroll
    for (int e = 0; e < NE; e++) acc[e] = 0.f;

    for (int h = lane; h < HD; h += 32) {
        float xv = xp[h];
        const float4* r = (const float4*)(rw + (size_t)h * NE);
        float4 a = r[0], b = r[1];
        acc[0] += xv * a.x; acc[1] += xv * a.y; acc[2] += xv * a.z; acc[3] += xv * a.w;
        acc[4] += xv * b.x; acc[5] += xv * b.y; acc[6] += xv * b.z; acc[7] += xv * b.w;
    }
#pragma unroll
    for (int e = 0; e < NE; e++)
#pragma unroll
        for (int o = 16; o > 0; o >>= 1)
            acc[e] += __shfl_xor_sync(0xffffffffu, acc[e], o);

    if (lane == 0) {
        float l[NE];
#pragma unroll
        for (int e = 0; e < NE; e++) l[e] = acc[e] + rb[e];
        int i1 = 0;
#pragma unroll
        for (int e = 1; e < NE; e++) if (l[e] > l[i1]) i1 = e;
        int i2 = (i1 == 0) ? 1 : 0;
#pragma unroll
        for (int e = 0; e < NE; e++) if (e != i1 && l[e] > l[i2]) i2 = e;

        float d  = expf(l[i2] - l[i1]);
        float w1 = 1.f / (1.f + d);
        float w2 = d * w1;
        g_topi[2 * t + 0] = i1; g_topw[2 * t + 0] = w1;
        g_topi[2 * t + 1] = i2; g_topw[2 * t + 1] = w2;
        atomicAdd(&g_cnt[i1], 1);
        atomicAdd(&g_cnt[i2], 1);
    }
}

__global__ void prefix_kernel() {
    if (threadIdx.x == 0) {
        int s = 0;
        for (int e = 0; e < NE; e++) { g_off[e] = s; g_cur[e] = s; s += g_cnt[e]; }
    }
}

__global__ void scatter_kernel() {
    int t = blockIdx.x * blockDim.x + threadIdx.x;
    if (t >= TT) return;
#pragma unroll
    for (int k = 0; k < 2; k++) {
        int e = g_topi[2 * t + k];
        int p = atomicAdd(&g_cur[e], 1);
        g_perm[p] = t;
        g_gw[p]   = g_topw[2 * t + k];
    }
}

// ---------------------------------------------------------------------------
// Grouped HMMA GEMM, fp32 inputs split to bf16 hi/lo IN-KERNEL during staging.
// 3 passes (hi*hi + hi*lo + lo*hi), fp32 accumulators.
// B is consumed directly from the [K][N] fp32 weights via ldmatrix.trans.
// MODE 0: h1[slot] = gelu(gather(x) @ w1[e] + b1[e])   (K=HD, N=FD, h1 fp32)
// MODE 1: out[tok] += gw * (h1[slot] @ w2[e] + b2[e])  (K=FD, N=HD, atomics)
// ---------------------------------------------------------------------------
template <int MODE>
__global__ void __launch_bounds__(256) moe_mma_kernel(
    const float* __restrict__ xsrc,   // x (MODE0) / unused (MODE1)
    const float* __restrict__ wsrc,   // w1 / w2, layout [E][K][N]
    const float* __restrict__ bias,
    float* __restrict__ out)
{
    constexpr int KD     = (MODE == 0) ? HD : FD;
    constexpr int ND     = (MODE == 0) ? FD : HD;
    constexpr int NCHUNK = KD / BK;

    __shared__ __align__(16) char smem[SMEMB];
    const uint32_t sb = smem_u32(smem);

    const int e       = blockIdx.z;
    const int seg_len = g_cnt[e];
    const int m0      = blockIdx.x * BM;
    if (m0 >= seg_len) return;
    const int seg_off = g_off[e];
    const int n0      = blockIdx.y * BN;
    const int tid     = threadIdx.x;

    // ---- staging assignment ----
    // A: thread -> (row 0..127, k-half 0/1), 16 fp32 each
    const int arow = tid >> 1, ahalf = tid & 1;
    const float* aptr;
    {
        int gr = m0 + arow;
        int cg = (gr < seg_len) ? gr : (seg_len - 1);
        if (MODE == 0) aptr = xsrc + (size_t)g_perm[seg_off + cg] * HD;
        else           aptr = g_h1 + (size_t)(seg_off + cg) * FD;
        aptr += ahalf * 16;
    }
    // B: thread -> (k-row 0..31, n-seg of 16), 16 fp32 each
    const int brow = tid >> 3, bseg = (tid & 7) * 16;
    const float* bptr = wsrc + (size_t)e * KD * ND + (size_t)brow * ND + n0 + bseg;

    uint4* aHiD = (uint4*)(smem + ASMOFF + arow * ROWA + ahalf * 32);
    uint4* aLoD = (uint4*)(smem + ASMOFF + arow * ROWA + 64 + ahalf * 32);
    uint4* bHiD = (uint4*)(smem + BSMOFF + brow * ROWBB + bseg * 2);
    uint4* bLoD = (uint4*)(smem + BSMOFF + brow * ROWBB + 256 + bseg * 2);

    // ---- fragment addressing ----
    const int wid = tid >> 5, lane = tid & 31;
    const int wM = wid & 3, wN = wid >> 2;   // 4 x 2 warp grid, warp tile 32x64
    // A (non-trans, m16k16): lanes 0-15 rows, 16-31 rows +16B (k8-15)
    const uint32_t aF = sb + (uint32_t)((wM * 32 + (lane & 15)) * ROWA
                                        + (lane >> 4) * 16);
    // B (trans): matrices (k0-7,n0-7),(k8-15,n0-7),(k0-7,n8-15),(k8-15,n8-15)
    const int bkrow = (lane & 7) + ((lane >> 3) & 1) * 8;
    const int bnoff = (lane >> 4) * 8;
    const uint32_t bF = sb + (uint32_t)BSMOFF
                      + (uint32_t)(bkrow * ROWBB + (wN * 64 + bnoff) * 2);

    float acc[2][8][4];
#pragma unroll
    for (int mf = 0; mf < 2; mf++)
#pragma unroll
        for (int nf = 0; nf < 8; nf++)
#pragma unroll
            for (int r = 0; r < 4; r++) acc[mf][nf][r] = 0.f;

    float4 pa[4], pb[4];
    auto ldA = [&](int kt) {
        const float4* p = (const float4*)(aptr + kt);
#pragma unroll
        for (int i = 0; i < 4; i++) pa[i] = p[i];
    };
    auto ldB = [&](int kt) {
        const float4* p = (const float4*)(bptr + (size_t)kt * ND);
#pragma unroll
        for (int i = 0; i < 4; i++) pb[i] = p[i];
    };
    auto stStage = [&]() {
        uint32_t h[8], l[8];
#pragma unroll
        for (int i = 0; i < 4; i++) {
            split2(pa[i].x, pa[i].y, h[2 * i], l[2 * i]);
            split2(pa[i].z, pa[i].w, h[2 * i + 1], l[2 * i + 1]);
        }
        aHiD[0] = make_uint4(h[0], h[1], h[2], h[3]);
        aHiD[1] = make_uint4(h[4], h[5], h[6], h[7]);
        aLoD[0] = make_uint4(l[0], l[1], l[2], l[3]);
        aLoD[1] = make_uint4(l[4], l[5], l[6], l[7]);
#pragma unroll
        for (int i = 0; i < 4; i++) {
            split2(pb[i].x, pb[i].y, h[2 * i], l[2 * i]);
            split2(pb[i].z, pb[i].w, h[2 * i + 1], l[2 * i + 1]);
        }
        bHiD[0] = make_uint4(h[0], h[1], h[2], h[3]);
        bHiD[1] = make_uint4(h[4], h[5], h[6], h[7]);
        bLoD[0] = make_uint4(l[0], l[1], l[2], l[3]);
        bLoD[1] = make_uint4(l[4], l[5], l[6], l[7]);
    };

    ldA(0); ldB(0);

#pragma unroll 1
    for (int c = 0; c < NCHUNK; c++) {
        __syncthreads();            // previous chunk's MMAs done; smem free
        stStage();
        __syncthreads();
        if (c + 1 < NCHUNK) { ldA((c + 1) * BK); ldB((c + 1) * BK); }

#pragma unroll
        for (int k16 = 0; k16 < 2; k16++) {
            uint32_t ah[2][4], al[2][4];
            const uint32_t ka = aF + (uint32_t)(k16 * 32);
            ldsm4(ka,                  ah[0]);
            ldsm4(ka + 16 * ROWA,      ah[1]);
            ldsm4(ka + 64,             al[0]);
            ldsm4(ka + 64 + 16 * ROWA, al[1]);
            const uint32_t kb = bF + (uint32_t)(k16 * 16 * ROWBB);
#pragma unroll
            for (int g2 = 0; g2 < 4; g2++) {
                uint32_t bh[4], bl[4];
                ldsm4t(kb + g2 * 32,       bh);
                ldsm4t(kb + 256 + g2 * 32, bl);
#pragma unroll
                for (int mf = 0; mf < 2; mf++) {
                    mma16816(acc[mf][2 * g2 + 0], ah[mf], bh[0], bh[1]);
                    mma16816(acc[mf][2 * g2 + 1], ah[mf], bh[2], bh[3]);
                    mma16816(acc[mf][2 * g2 + 0], ah[mf], bl[0], bl[1]);
                    mma16816(acc[mf][2 * g2 + 1], ah[mf], bl[2], bl[3]);
                    mma16816(acc[mf][2 * g2 + 0], al[mf], bh[0], bh[1]);
                    mma16816(acc[mf][2 * g2 + 1], al[mf], bh[2], bh[3]);
                }
            }
        }
    }

    // ---- epilogue ----
    // D frag: thread holds rows (lane>>2), (lane>>2)+8; cols (lane&3)*2, +1
    const float* bp = bias + (size_t)e * ND + n0 + wN * 64 + (lane & 3) * 2;
    float bv[16];
#pragma unroll
    for (int nf = 0; nf < 8; nf++) {
        bv[2 * nf + 0] = __ldg(bp + nf * 8);
        bv[2 * nf + 1] = __ldg(bp + nf * 8 + 1);
    }
    const int colBase = n0 + wN * 64 + (lane & 3) * 2;

#pragma unroll
    for (int mf = 0; mf < 2; mf++) {
#pragma unroll
        for (int half = 0; half < 2; half++) {
            int gr = m0 + wM * 32 + mf * 16 + (lane >> 2) + half * 8;
            if (gr >= seg_len) continue;
            int slot = seg_off + gr;
            if (MODE == 0) {
                float* op = g_h1 + (size_t)slot * FD;
#pragma unroll
                for (int nf = 0; nf < 8; nf++) {
                    float v0 = acc[mf][nf][2 * half + 0] + bv[2 * nf + 0];
                    float v1 = acc[mf][nf][2 * half + 1] + bv[2 * nf + 1];
                    float c0 = v0 + 0.044715f * v0 * v0 * v0;
                    float c1 = v1 + 0.044715f * v1 * v1 * v1;
                    float g0 = 0.5f * v0 * (1.f + tanhf(0.7978845608028654f * c0));
                    float g1 = 0.5f * v1 * (1.f + tanhf(0.7978845608028654f * c1));
                    *(float2*)(op + colBase + nf * 8) = make_float2(g0, g1);
                }
            } else {
                int   tok = g_perm[slot];
                float w   = g_gw[slot];
                float* op = out + (size_t)tok * HD;
#pragma unroll
                for (int nf = 0; nf < 8; nf++) {
                    int col = colBase + nf * 8;
                    atomicAdd(op + col,
                              w * (acc[mf][nf][2 * half + 0] + bv[2 * nf + 0]));
                    atomicAdd(op + col + 1,
                              w * (acc[mf][nf][2 * half + 1] + bv[2 * nf + 1]));
                }
            }
        }
    }
}

// ---------------------------------------------------------------------------
// Launch
// ---------------------------------------------------------------------------
extern "C" void kernel_launch(void* const* d_in, const int* in_sizes, int n_in,
                              void* d_out, int out_size) {
    const float* x  = (const float*)d_in[0];   // [B,S,H]
    const float* w1 = (const float*)d_in[1];   // [E,H,F]  = [E][K][N] for GEMM1
    const float* b1 = (const float*)d_in[2];   // [E,F]
    const float* w2 = (const float*)d_in[3];   // [E,F,H]  = [E][K][N] for GEMM2
    const float* b2 = (const float*)d_in[4];   // [E,H]
    const float* rw = (const float*)d_in[5];   // [H,E]
    const float* rb = (const float*)d_in[6];   // [E]
    float* out = (float*)d_out;

    zero_kernel<<<4096, 256>>>((float4*)out);
    router_kernel<<<TT / 8, 256>>>(x, rw, rb);
    prefix_kernel<<<1, 32>>>();
    scatter_kernel<<<TT / 256, 256>>>();

    // GEMM1: gelu(gather(x) @ w1 + b1) -> h1 (fp32)
    moe_mma_kernel<0><<<dim3(128, FD / BN, NE), 256>>>(x, w1, b1, nullptr);
    // GEMM2: h1 @ w2 + b2, weighted atomic combine into out
    moe_mma_kernel<1><<<dim3(128, HD / BN, NE), 256>>>(x, w2, b2, out);
}